// round 1
// baseline (speedup 1.0000x reference)
#include <cuda_runtime.h>
#include <math.h>

// Problem constants
#define BB   8
#define TT   2048
#define ROWS (BB * TT)      // 16384
#define DIN  64
#define DM   256
#define DI   512
#define NST  16
#define RR   16
#define DOUT 128
#define DBCN 48             // R + 2N
#define LAY  2

// ---------------------------------------------------------------------------
// Scratch (static device globals — no runtime allocation allowed)
// ---------------------------------------------------------------------------
__device__ float g_h  [ROWS * DM];        // layer activations (in_proj out / layer out)
__device__ float g_xz [ROWS * 2 * DI];    // xz = h@Win + bin
__device__ float g_xc [ROWS * DI];        // conv+silu output
__device__ float g_dbc[ROWS * DBCN];      // xc @ Wx
__device__ float g_dt [ROWS * DI];        // softplus(dbc[:, :R] @ Wdt + bdt)
__device__ float g_y  [ROWS * DI];        // scan output, then gated in-place

// ---------------------------------------------------------------------------
// Generic fp32 SGEMM: C[M,N] = A[M,K] @ B[K,N] (+ bias[N] optional)
// 128x128 tile, BK=8, 256 threads, 8x8 per thread (4 quadrants of 4x4).
// Requires K % 8 == 0, N % 4 == 0. M/N edges guarded.
// ---------------------------------------------------------------------------
__global__ __launch_bounds__(256) void sgemm128(
    const float* __restrict__ A, const float* __restrict__ Bm,
    const float* __restrict__ bias, float* __restrict__ C,
    int M, int N, int K)
{
    __shared__ float As[8][128];
    __shared__ float Bs[8][128];

    const int tid  = threadIdx.x;
    const int brow = blockIdx.y * 128;
    const int bcol = blockIdx.x * 128;
    const int tx = tid & 15;
    const int ty = tid >> 4;

    const int arow = tid >> 1;          // 0..127
    const int acol = (tid & 1) * 4;     // 0 or 4
    const int brl  = tid >> 5;          // 0..7
    const int bcl  = (tid & 31) * 4;    // 0..124

    float acc[8][8];
#pragma unroll
    for (int i = 0; i < 8; i++)
#pragma unroll
        for (int j = 0; j < 8; j++) acc[i][j] = 0.f;

    for (int k0 = 0; k0 < K; k0 += 8) {
        // load A tile (transpose into As)
        float4 av = make_float4(0.f, 0.f, 0.f, 0.f);
        int gar = brow + arow;
        if (gar < M)
            av = *(const float4*)&A[(size_t)gar * K + k0 + acol];
        As[acol + 0][arow] = av.x;
        As[acol + 1][arow] = av.y;
        As[acol + 2][arow] = av.z;
        As[acol + 3][arow] = av.w;
        // load B tile
        float4 bv = make_float4(0.f, 0.f, 0.f, 0.f);
        int gbc = bcol + bcl;
        if (gbc < N)
            bv = *(const float4*)&Bm[(size_t)(k0 + brl) * N + gbc];
        *(float4*)&Bs[brl][bcl] = bv;
        __syncthreads();

#pragma unroll
        for (int k = 0; k < 8; k++) {
            float4 a0 = *(float4*)&As[k][ty * 4];
            float4 a1 = *(float4*)&As[k][ty * 4 + 64];
            float4 b0 = *(float4*)&Bs[k][tx * 4];
            float4 b1 = *(float4*)&Bs[k][tx * 4 + 64];
            float a[8] = {a0.x, a0.y, a0.z, a0.w, a1.x, a1.y, a1.z, a1.w};
            float b[8] = {b0.x, b0.y, b0.z, b0.w, b1.x, b1.y, b1.z, b1.w};
#pragma unroll
            for (int i = 0; i < 8; i++)
#pragma unroll
                for (int j = 0; j < 8; j++)
                    acc[i][j] += a[i] * b[j];
        }
        __syncthreads();
    }

    // epilogue
#pragma unroll
    for (int i = 0; i < 8; i++) {
        int row = brow + ty * 4 + (i & 3) + ((i >= 4) ? 64 : 0);
        if (row >= M) continue;
#pragma unroll
        for (int jh = 0; jh < 2; jh++) {
            int col = bcol + tx * 4 + jh * 64;
            if (col < N) {
                float4 o;
                float b0 = bias ? bias[col + 0] : 0.f;
                float b1 = bias ? bias[col + 1] : 0.f;
                float b2 = bias ? bias[col + 2] : 0.f;
                float b3 = bias ? bias[col + 3] : 0.f;
                o.x = acc[i][jh * 4 + 0] + b0;
                o.y = acc[i][jh * 4 + 1] + b1;
                o.z = acc[i][jh * 4 + 2] + b2;
                o.w = acc[i][jh * 4 + 3] + b3;
                *(float4*)&C[(size_t)row * N + col] = o;
            }
        }
    }
}

// ---------------------------------------------------------------------------
// Depthwise causal conv (K=4) + SiLU.  xi = g_xz[:, :DI]
// ---------------------------------------------------------------------------
__global__ void conv_silu(const float* __restrict__ cw,   // (DI,4) for layer
                          const float* __restrict__ cb)   // (DI,)
{
    int idx = blockIdx.x * blockDim.x + threadIdx.x;   // ROWS*DI
    if (idx >= ROWS * DI) return;
    int d   = idx & (DI - 1);
    int row = idx >> 9;            // b*T + t
    int t   = row & (TT - 1);

    const float* xi = g_xz + (size_t)row * (2 * DI) + d;
    float w0 = cw[d * 4 + 0], w1 = cw[d * 4 + 1];
    float w2 = cw[d * 4 + 2], w3 = cw[d * 4 + 3];

    float acc = cb[d] + w3 * xi[0];
    if (t >= 1) acc += w2 * xi[-(2 * DI)];
    if (t >= 2) acc += w1 * xi[-(4 * DI)];
    if (t >= 3) acc += w0 * xi[-(6 * DI)];

    float s = acc / (1.f + expf(-acc));   // silu
    g_xc[idx] = s;
}

// ---------------------------------------------------------------------------
// dt = softplus(dbc[:, :R] @ Wdt + bdt)
// ---------------------------------------------------------------------------
__global__ void dt_softplus(const float* __restrict__ Wdt,  // (R, DI) layer slice
                            const float* __restrict__ bdt)  // (DI,)
{
    int idx = blockIdx.x * blockDim.x + threadIdx.x;   // ROWS*DI
    if (idx >= ROWS * DI) return;
    int d   = idx & (DI - 1);
    int row = idx >> 9;

    const float* db = g_dbc + (size_t)row * DBCN;
    float acc = bdt[d];
#pragma unroll
    for (int r = 0; r < RR; r++)
        acc += db[r] * Wdt[r * DI + d];

    float dt = (acc > 20.f) ? acc : log1pf(expf(acc));
    g_dt[idx] = dt;
}

// ---------------------------------------------------------------------------
// Selective scan. 16 threads per (b,d) lane, one state per thread.
// grid = BB * (DI/32) = 128 blocks, 512 threads (32 d-lanes per block).
// ---------------------------------------------------------------------------
__global__ __launch_bounds__(512) void ssm_scan(const float* __restrict__ A_log_l)
{
    int b    = blockIdx.x >> 4;        // /16
    int dgrp = blockIdx.x & 15;
    int n    = threadIdx.x & 15;
    int dl   = threadIdx.x >> 4;       // 0..31
    int d    = dgrp * 32 + dl;

    float a = -expf(A_log_l[d * NST + n]);

    const float* dtp = g_dt  + (size_t)b * TT * DI + d;
    const float* xp  = g_xc  + (size_t)b * TT * DI + d;
    const float* dbp = g_dbc + (size_t)b * TT * DBCN;
    float*       yp  = g_y   + (size_t)b * TT * DI + d;

    float h = 0.f;
    for (int t = 0; t < TT; t++) {
        float dt = dtp[(size_t)t * DI];
        float x  = xp [(size_t)t * DI];
        float Bv = dbp[t * DBCN + RR + n];
        float Cv = dbp[t * DBCN + RR + NST + n];

        float dA = expf(dt * a);
        h = dA * h + (dt * x) * Bv;

        float pv = h * Cv;
        pv += __shfl_xor_sync(0xffffffffu, pv, 1);
        pv += __shfl_xor_sync(0xffffffffu, pv, 2);
        pv += __shfl_xor_sync(0xffffffffu, pv, 4);
        pv += __shfl_xor_sync(0xffffffffu, pv, 8);
        if (n == 0) yp[(size_t)t * DI] = pv;
    }
}

// ---------------------------------------------------------------------------
// Gating: y = (y + Dp*xc) * silu(z),  z = g_xz[:, DI:]
// ---------------------------------------------------------------------------
__global__ void gate_silu(const float* __restrict__ Dp)   // (DI,)
{
    int idx = blockIdx.x * blockDim.x + threadIdx.x;
    if (idx >= ROWS * DI) return;
    int d   = idx & (DI - 1);
    int row = idx >> 9;

    float z  = g_xz[(size_t)row * (2 * DI) + DI + d];
    float sz = z / (1.f + expf(-z));
    g_y[idx] = (g_y[idx] + Dp[d] * g_xc[idx]) * sz;
}

// ---------------------------------------------------------------------------
// Final: mean over T, then @ W_out_proj + b_out_proj -> out (8,128)
// ---------------------------------------------------------------------------
__global__ void mean_proj(const float* __restrict__ Wop,
                          const float* __restrict__ bop,
                          float* __restrict__ out)
{
    __shared__ float hm[DM];
    int b = blockIdx.x;
    int c = threadIdx.x;        // 256 threads

    float s = 0.f;
    const float* hp = g_h + (size_t)b * TT * DM + c;
    for (int t = 0; t < TT; t++)
        s += hp[(size_t)t * DM];
    hm[c] = s * (1.f / (float)TT);
    __syncthreads();

    if (c < DOUT) {
        float acc = bop[c];
#pragma unroll 4
        for (int k = 0; k < DM; k++)
            acc += hm[k] * Wop[k * DOUT + c];
        out[b * DOUT + c] = acc;
    }
}

// ---------------------------------------------------------------------------
// Orchestration
// ---------------------------------------------------------------------------
static void launch_sgemm(const float* A, const float* B, const float* bias,
                         float* C, int M, int N, int K)
{
    dim3 grid((N + 127) / 128, (M + 127) / 128);
    sgemm128<<<grid, 256>>>(A, B, bias, C, M, N, K);
}

extern "C" void kernel_launch(void* const* d_in, const int* in_sizes, int n_in,
                              void* d_out, int out_size)
{
    const float* x        = (const float*)d_in[0];   // (8,2048,64)
    const float* W_in     = (const float*)d_in[1];   // (64,256)
    const float* b_in     = (const float*)d_in[2];   // (256)
    const float* Win      = (const float*)d_in[3];   // (2,256,1024)
    const float* bin_     = (const float*)d_in[4];   // (2,1024)
    const float* conv_w   = (const float*)d_in[5];   // (2,512,4)
    const float* conv_b   = (const float*)d_in[6];   // (2,512)
    const float* Wx       = (const float*)d_in[7];   // (2,512,48)
    const float* Wdt      = (const float*)d_in[8];   // (2,16,512)
    const float* bdt      = (const float*)d_in[9];   // (2,512)
    const float* A_log    = (const float*)d_in[10];  // (2,512,16)
    const float* Dp       = (const float*)d_in[11];  // (2,512)
    const float* Wout     = (const float*)d_in[12];  // (2,512,256)
    const float* W_op     = (const float*)d_in[13];  // (256,128)
    const float* b_op     = (const float*)d_in[14];  // (128)
    float* out = (float*)d_out;

    float *hbuf, *xzbuf, *xcbuf, *dbcbuf, *dtbuf, *ybuf;
    cudaGetSymbolAddress((void**)&hbuf,   g_h);
    cudaGetSymbolAddress((void**)&xzbuf,  g_xz);
    cudaGetSymbolAddress((void**)&xcbuf,  g_xc);
    cudaGetSymbolAddress((void**)&dbcbuf, g_dbc);
    cudaGetSymbolAddress((void**)&dtbuf,  g_dt);
    cudaGetSymbolAddress((void**)&ybuf,   g_y);

    const int EW_BLOCKS = (ROWS * DI + 255) / 256;

    // in_proj: h = x @ W_in + b_in
    launch_sgemm(x, W_in, b_in, hbuf, ROWS, DM, DIN);

    for (int l = 0; l < LAY; l++) {
        const float* Win_l  = Win    + (size_t)l * DM * 2 * DI;
        const float* bin_l  = bin_   + (size_t)l * 2 * DI;
        const float* cw_l   = conv_w + (size_t)l * DI * 4;
        const float* cb_l   = conv_b + (size_t)l * DI;
        const float* Wx_l   = Wx     + (size_t)l * DI * DBCN;
        const float* Wdt_l  = Wdt    + (size_t)l * RR * DI;
        const float* bdt_l  = bdt    + (size_t)l * DI;
        const float* Alog_l = A_log  + (size_t)l * DI * NST;
        const float* Dp_l   = Dp     + (size_t)l * DI;
        const float* Wout_l = Wout   + (size_t)l * DI * DM;

        // xz = h @ Win + bin
        launch_sgemm(hbuf, Win_l, bin_l, xzbuf, ROWS, 2 * DI, DM);
        // xc = silu(causal depthwise conv(xi) + conv_b)
        conv_silu<<<EW_BLOCKS, 256>>>(cw_l, cb_l);
        // dbc = xc @ Wx
        launch_sgemm(xcbuf, Wx_l, nullptr, dbcbuf, ROWS, DBCN, DI);
        // dt = softplus(dbc[:, :R] @ Wdt + bdt)
        dt_softplus<<<EW_BLOCKS, 256>>>(Wdt_l, bdt_l);
        // selective scan -> g_y
        ssm_scan<<<BB * (DI / 32), 512>>>(Alog_l);
        // y = (y + Dp*xc) * silu(z)
        gate_silu<<<EW_BLOCKS, 256>>>(Dp_l);
        // h = y @ Wout   (overwrites g_h; safe, h no longer needed)
        launch_sgemm(ybuf, Wout_l, nullptr, hbuf, ROWS, DM, DI);
    }

    // out = mean_T(h) @ W_out_proj + b_out_proj
    mean_proj<<<BB, DM>>>(W_op, b_op, out);
}

// round 2
// speedup vs baseline: 1.1627x; 1.1627x over previous
#include <cuda_runtime.h>
#include <math.h>
#include <mma.h>

using namespace nvcuda;

// Problem constants
#define BB   8
#define TT   2048
#define ROWS (BB * TT)      // 16384
#define DIN  64
#define DM   256
#define DI   512
#define NST  16
#define RR   16
#define DOUT 128
#define DBCN 48             // R + 2N
#define LAY  2

// ---------------------------------------------------------------------------
// Scratch (static device globals — no runtime allocation allowed)
// ---------------------------------------------------------------------------
__device__ float g_h  [ROWS * DM];
__device__ float g_xz [ROWS * 2 * DI];
__device__ float g_xc [ROWS * DI];
__device__ float g_dbc[ROWS * DBCN];
__device__ float g_dt [ROWS * DI];
__device__ float g_y  [ROWS * DI];

// ---------------------------------------------------------------------------
// TF32 tensor-core GEMM: C[M,N] = A[M,K] @ B[K,N] (+ bias optional)
// BM=128, BK=16, BN template (128 or 64). 256 threads = 8 warps.
// Warp grid 4x2; warp tile 32 x (BN/2). Double-buffered smem.
// Requires: M % 128 == 0, K % 16 == 0 (true for all uses). N edges guarded.
// ---------------------------------------------------------------------------
template<int BN>
__global__ __launch_bounds__(256) void tgemm(
    const float* __restrict__ A, const float* __restrict__ B,
    const float* __restrict__ bias, float* __restrict__ C,
    int M, int N, int K)
{
    constexpr int BM  = 128, BK = 16;
    constexpr int LDA = BK + 4;          // padded leading dims (floats)
    constexpr int LDB = BN + 4;
    constexpr int WN  = BN / 2;          // warp tile N
    constexpr int NF  = WN / 16;         // b-fragments per warp
    constexpr int NB4 = BN / 4;          // float4 per B smem row
    constexpr int BL  = (BK * BN / 4 + 255) / 256;  // B float4 loads per thread

    __shared__ float As[2][BM * LDA];
    __shared__ float Bs[2][BK * LDB];
    __shared__ float Ep[8][256];

    const int tid  = threadIdx.x;
    const int lane = tid & 31;
    const int wid  = tid >> 5;
    const int wm   = wid & 3;            // 0..3
    const int wn   = wid >> 2;           // 0..1
    const int brow = blockIdx.y * BM;
    const int bcol = blockIdx.x * BN;

    wmma::fragment<wmma::accumulator, 16, 16, 8, float> acc[2][NF];
#pragma unroll
    for (int i = 0; i < 2; i++)
#pragma unroll
        for (int j = 0; j < NF; j++)
            wmma::fill_fragment(acc[i][j], 0.f);

    // A tile load mapping: 512 float4 over 256 threads (2 each)
    const int ar0 = tid >> 2,          ac0 = (tid & 3) * 4;
    const int ar1 = (tid + 256) >> 2,  ac1 = (tid & 3) * 4;  // same col pattern

    float4 aR0, aR1;
    float4 bR[BL];

    auto loadA = [&](int k0) {
        aR0 = *(const float4*)&A[(size_t)(brow + ar0) * K + k0 + ac0];
        aR1 = *(const float4*)&A[(size_t)(brow + ar1) * K + k0 + ac1];
    };
    auto loadB = [&](int k0) {
#pragma unroll
        for (int u = 0; u < BL; u++) {
            int idx = tid + 256 * u;
            int r = idx / NB4, c = (idx % NB4) * 4;
            int gc = bcol + c;
            if (gc + 4 <= N) {
                bR[u] = *(const float4*)&B[(size_t)(k0 + r) * N + gc];
            } else {
                float v0 = (gc + 0 < N) ? B[(size_t)(k0 + r) * N + gc + 0] : 0.f;
                float v1 = (gc + 1 < N) ? B[(size_t)(k0 + r) * N + gc + 1] : 0.f;
                float v2 = (gc + 2 < N) ? B[(size_t)(k0 + r) * N + gc + 2] : 0.f;
                float v3 = (gc + 3 < N) ? B[(size_t)(k0 + r) * N + gc + 3] : 0.f;
                bR[u] = make_float4(v0, v1, v2, v3);
            }
        }
    };
    auto storeS = [&](int buf) {
        As[buf][ar0 * LDA + ac0 + 0] = wmma::__float_to_tf32(aR0.x);
        As[buf][ar0 * LDA + ac0 + 1] = wmma::__float_to_tf32(aR0.y);
        As[buf][ar0 * LDA + ac0 + 2] = wmma::__float_to_tf32(aR0.z);
        As[buf][ar0 * LDA + ac0 + 3] = wmma::__float_to_tf32(aR0.w);
        As[buf][ar1 * LDA + ac1 + 0] = wmma::__float_to_tf32(aR1.x);
        As[buf][ar1 * LDA + ac1 + 1] = wmma::__float_to_tf32(aR1.y);
        As[buf][ar1 * LDA + ac1 + 2] = wmma::__float_to_tf32(aR1.z);
        As[buf][ar1 * LDA + ac1 + 3] = wmma::__float_to_tf32(aR1.w);
#pragma unroll
        for (int u = 0; u < BL; u++) {
            int idx = tid + 256 * u;
            int r = idx / NB4, c = (idx % NB4) * 4;
            Bs[buf][r * LDB + c + 0] = wmma::__float_to_tf32(bR[u].x);
            Bs[buf][r * LDB + c + 1] = wmma::__float_to_tf32(bR[u].y);
            Bs[buf][r * LDB + c + 2] = wmma::__float_to_tf32(bR[u].z);
            Bs[buf][r * LDB + c + 3] = wmma::__float_to_tf32(bR[u].w);
        }
    };
    auto compute = [&](int buf) {
#pragma unroll
        for (int kk = 0; kk < BK; kk += 8) {
            wmma::fragment<wmma::matrix_a, 16, 16, 8, wmma::precision::tf32,
                           wmma::row_major> af[2];
            wmma::fragment<wmma::matrix_b, 16, 16, 8, wmma::precision::tf32,
                           wmma::row_major> bf[NF];
#pragma unroll
            for (int i = 0; i < 2; i++)
                wmma::load_matrix_sync(af[i],
                    &As[buf][(wm * 32 + i * 16) * LDA + kk], LDA);
#pragma unroll
            for (int j = 0; j < NF; j++)
                wmma::load_matrix_sync(bf[j],
                    &Bs[buf][kk * LDB + wn * WN + j * 16], LDB);
#pragma unroll
            for (int i = 0; i < 2; i++)
#pragma unroll
                for (int j = 0; j < NF; j++)
                    wmma::mma_sync(acc[i][j], af[i], bf[j], acc[i][j]);
        }
    };

    // mainloop (double buffered)
    loadA(0); loadB(0);
    int buf = 0;
    storeS(buf);
    __syncthreads();
    for (int k0 = 0; k0 < K; k0 += BK) {
        bool last = (k0 + BK >= K);
        if (!last) { loadA(k0 + BK); loadB(k0 + BK); }
        compute(buf);
        if (!last) storeS(buf ^ 1);
        __syncthreads();
        buf ^= 1;
    }

    // epilogue: stage each 16x16 fragment through per-warp smem, add bias
    const int er = lane >> 1;           // 0..15
    const int ec = (lane & 1) * 8;      // 0 or 8
#pragma unroll
    for (int i = 0; i < 2; i++) {
#pragma unroll
        for (int j = 0; j < NF; j++) {
            wmma::store_matrix_sync(Ep[wid], acc[i][j], 16, wmma::mem_row_major);
            __syncwarp();
            int gr = brow + wm * 32 + i * 16 + er;
            int gc = bcol + wn * WN + j * 16 + ec;
            float v[8];
#pragma unroll
            for (int q = 0; q < 8; q++)
                v[q] = Ep[wid][er * 16 + ec + q] +
                       (bias ? ((gc + q < N) ? bias[gc + q] : 0.f) : 0.f);
            if (gc + 8 <= N) {
                *(float4*)&C[(size_t)gr * N + gc]     = make_float4(v[0], v[1], v[2], v[3]);
                *(float4*)&C[(size_t)gr * N + gc + 4] = make_float4(v[4], v[5], v[6], v[7]);
            } else {
#pragma unroll
                for (int q = 0; q < 8; q++)
                    if (gc + q < N) C[(size_t)gr * N + gc + q] = v[q];
            }
            __syncwarp();
        }
    }
}

// ---------------------------------------------------------------------------
// Depthwise causal conv (K=4) + SiLU.  xi = g_xz[:, :DI]
// ---------------------------------------------------------------------------
__global__ void conv_silu(const float* __restrict__ cw,
                          const float* __restrict__ cb)
{
    int idx = blockIdx.x * blockDim.x + threadIdx.x;
    if (idx >= ROWS * DI) return;
    int d   = idx & (DI - 1);
    int row = idx >> 9;
    int t   = row & (TT - 1);

    const float* xi = g_xz + (size_t)row * (2 * DI) + d;
    float w0 = cw[d * 4 + 0], w1 = cw[d * 4 + 1];
    float w2 = cw[d * 4 + 2], w3 = cw[d * 4 + 3];

    float acc = cb[d] + w3 * xi[0];
    if (t >= 1) acc += w2 * xi[-(2 * DI)];
    if (t >= 2) acc += w1 * xi[-(4 * DI)];
    if (t >= 3) acc += w0 * xi[-(6 * DI)];

    g_xc[idx] = acc / (1.f + expf(-acc));
}

// ---------------------------------------------------------------------------
// dt = softplus(dbc[:, :R] @ Wdt + bdt)
// ---------------------------------------------------------------------------
__global__ void dt_softplus(const float* __restrict__ Wdt,
                            const float* __restrict__ bdt)
{
    int idx = blockIdx.x * blockDim.x + threadIdx.x;
    if (idx >= ROWS * DI) return;
    int d   = idx & (DI - 1);
    int row = idx >> 9;

    const float* db = g_dbc + (size_t)row * DBCN;
    float acc = bdt[d];
#pragma unroll
    for (int r = 0; r < RR; r++)
        acc += db[r] * Wdt[r * DI + d];

    g_dt[idx] = (acc > 20.f) ? acc : log1pf(expf(acc));
}

// ---------------------------------------------------------------------------
// Selective scan. 16 threads per (b,d) lane, one state per thread.
// ---------------------------------------------------------------------------
__global__ __launch_bounds__(512) void ssm_scan(const float* __restrict__ A_log_l)
{
    int b    = blockIdx.x >> 4;
    int dgrp = blockIdx.x & 15;
    int n    = threadIdx.x & 15;
    int dl   = threadIdx.x >> 4;
    int d    = dgrp * 32 + dl;

    float a = -expf(A_log_l[d * NST + n]);

    const float* dtp = g_dt  + (size_t)b * TT * DI + d;
    const float* xp  = g_xc  + (size_t)b * TT * DI + d;
    const float* dbp = g_dbc + (size_t)b * TT * DBCN;
    float*       yp  = g_y   + (size_t)b * TT * DI + d;

    float h = 0.f;
    for (int t = 0; t < TT; t++) {
        float dt = dtp[(size_t)t * DI];
        float x  = xp [(size_t)t * DI];
        float Bv = dbp[t * DBCN + RR + n];
        float Cv = dbp[t * DBCN + RR + NST + n];

        float dA = expf(dt * a);
        h = dA * h + (dt * x) * Bv;

        float pv = h * Cv;
        pv += __shfl_xor_sync(0xffffffffu, pv, 1);
        pv += __shfl_xor_sync(0xffffffffu, pv, 2);
        pv += __shfl_xor_sync(0xffffffffu, pv, 4);
        pv += __shfl_xor_sync(0xffffffffu, pv, 8);
        if (n == 0) yp[(size_t)t * DI] = pv;
    }
}

// ---------------------------------------------------------------------------
// Gating: y = (y + Dp*xc) * silu(z)
// ---------------------------------------------------------------------------
__global__ void gate_silu(const float* __restrict__ Dp)
{
    int idx = blockIdx.x * blockDim.x + threadIdx.x;
    if (idx >= ROWS * DI) return;
    int d   = idx & (DI - 1);
    int row = idx >> 9;

    float z  = g_xz[(size_t)row * (2 * DI) + DI + d];
    float sz = z / (1.f + expf(-z));
    g_y[idx] = (g_y[idx] + Dp[d] * g_xc[idx]) * sz;
}

// ---------------------------------------------------------------------------
// Final: mean over T, then @ W_out_proj + b_out_proj
// ---------------------------------------------------------------------------
__global__ void mean_proj(const float* __restrict__ Wop,
                          const float* __restrict__ bop,
                          float* __restrict__ out)
{
    __shared__ float hm[DM];
    int b = blockIdx.x;
    int c = threadIdx.x;

    float s = 0.f;
    const float* hp = g_h + (size_t)b * TT * DM + c;
    for (int t = 0; t < TT; t++)
        s += hp[(size_t)t * DM];
    hm[c] = s * (1.f / (float)TT);
    __syncthreads();

    if (c < DOUT) {
        float acc = bop[c];
#pragma unroll 4
        for (int k = 0; k < DM; k++)
            acc += hm[k] * Wop[k * DOUT + c];
        out[b * DOUT + c] = acc;
    }
}

// ---------------------------------------------------------------------------
// Orchestration
// ---------------------------------------------------------------------------
static void launch_tgemm128(const float* A, const float* B, const float* bias,
                            float* C, int M, int N, int K)
{
    dim3 grid((N + 127) / 128, (M + 127) / 128);
    tgemm<128><<<grid, 256>>>(A, B, bias, C, M, N, K);
}
static void launch_tgemm64(const float* A, const float* B, const float* bias,
                           float* C, int M, int N, int K)
{
    dim3 grid((N + 63) / 64, (M + 127) / 128);
    tgemm<64><<<grid, 256>>>(A, B, bias, C, M, N, K);
}

extern "C" void kernel_launch(void* const* d_in, const int* in_sizes, int n_in,
                              void* d_out, int out_size)
{
    const float* x        = (const float*)d_in[0];
    const float* W_in     = (const float*)d_in[1];
    const float* b_in     = (const float*)d_in[2];
    const float* Win      = (const float*)d_in[3];
    const float* bin_     = (const float*)d_in[4];
    const float* conv_w   = (const float*)d_in[5];
    const float* conv_b   = (const float*)d_in[6];
    const float* Wx       = (const float*)d_in[7];
    const float* Wdt      = (const float*)d_in[8];
    const float* bdt      = (const float*)d_in[9];
    const float* A_log    = (const float*)d_in[10];
    const float* Dp       = (const float*)d_in[11];
    const float* Wout     = (const float*)d_in[12];
    const float* W_op     = (const float*)d_in[13];
    const float* b_op     = (const float*)d_in[14];
    float* out = (float*)d_out;

    float *hbuf, *xzbuf, *xcbuf, *dbcbuf, *ybuf;
    cudaGetSymbolAddress((void**)&hbuf,   g_h);
    cudaGetSymbolAddress((void**)&xzbuf,  g_xz);
    cudaGetSymbolAddress((void**)&xcbuf,  g_xc);
    cudaGetSymbolAddress((void**)&dbcbuf, g_dbc);
    cudaGetSymbolAddress((void**)&ybuf,   g_y);

    const int EW_BLOCKS = (ROWS * DI + 255) / 256;

    // in_proj: h = x @ W_in + b_in
    launch_tgemm128(x, W_in, b_in, hbuf, ROWS, DM, DIN);

    for (int l = 0; l < LAY; l++) {
        const float* Win_l  = Win    + (size_t)l * DM * 2 * DI;
        const float* bin_l  = bin_   + (size_t)l * 2 * DI;
        const float* cw_l   = conv_w + (size_t)l * DI * 4;
        const float* cb_l   = conv_b + (size_t)l * DI;
        const float* Wx_l   = Wx     + (size_t)l * DI * DBCN;
        const float* Wdt_l  = Wdt    + (size_t)l * RR * DI;
        const float* bdt_l  = bdt    + (size_t)l * DI;
        const float* Alog_l = A_log  + (size_t)l * DI * NST;
        const float* Dp_l   = Dp     + (size_t)l * DI;
        const float* Wout_l = Wout   + (size_t)l * DI * DM;

        // xz = h @ Win + bin
        launch_tgemm128(hbuf, Win_l, bin_l, xzbuf, ROWS, 2 * DI, DM);
        // xc = silu(depthwise causal conv(xi) + conv_b)
        conv_silu<<<EW_BLOCKS, 256>>>(cw_l, cb_l);
        // dbc = xc @ Wx   (N=48 -> BN=64 variant)
        launch_tgemm64(xcbuf, Wx_l, nullptr, dbcbuf, ROWS, DBCN, DI);
        // dt = softplus(dbc[:, :R] @ Wdt + bdt)
        dt_softplus<<<EW_BLOCKS, 256>>>(Wdt_l, bdt_l);
        // selective scan -> g_y
        ssm_scan<<<BB * (DI / 32), 512>>>(Alog_l);
        // y = (y + Dp*xc) * silu(z)
        gate_silu<<<EW_BLOCKS, 256>>>(Dp_l);
        // h = y @ Wout
        launch_tgemm128(ybuf, Wout_l, nullptr, hbuf, ROWS, DM, DI);
    }

    mean_proj<<<BB, DM>>>(W_op, b_op, out);
}

// round 3
// speedup vs baseline: 2.0211x; 1.7383x over previous
#include <cuda_runtime.h>
#include <math.h>
#include <mma.h>

using namespace nvcuda;

// Problem constants
#define BB   8
#define TT   2048
#define ROWS (BB * TT)      // 16384
#define DIN  64
#define DM   256
#define DI   512
#define NST  16
#define RR   16
#define DOUT 128
#define DBCN 48             // R + 2N
#define LAY  2

// ---------------------------------------------------------------------------
// Scratch (static device globals)
// ---------------------------------------------------------------------------
__device__ float g_h  [ROWS * DM];
__device__ float g_xz [ROWS * 2 * DI];
__device__ float g_xc [ROWS * DI];
__device__ float g_dbc[ROWS * DBCN];
__device__ float g_dt [ROWS * DI];
__device__ float g_y  [ROWS * DI];

// ---------------------------------------------------------------------------
// TF32 tensor-core GEMM: C[M,N] = A[M,K] @ B[K,N] (+ bias optional)
// BM=128, BK=16, BN template (128 or 64). 256 threads = 8 warps, 2 CTAs/SM.
// ---------------------------------------------------------------------------
template<int BN>
__global__ __launch_bounds__(256, 2) void tgemm(
    const float* __restrict__ A, const float* __restrict__ B,
    const float* __restrict__ bias, float* __restrict__ C,
    int M, int N, int K)
{
    constexpr int BM  = 128, BK = 16;
    constexpr int LDA = BK + 4;
    constexpr int LDB = BN + 4;
    constexpr int WN  = BN / 2;
    constexpr int NF  = WN / 16;
    constexpr int NB4 = BN / 4;
    constexpr int BL  = (BK * BN / 4 + 255) / 256;

    __shared__ float As[2][BM * LDA];
    __shared__ float Bs[2][BK * LDB];
    __shared__ float Ep[8][256];

    const int tid  = threadIdx.x;
    const int lane = tid & 31;
    const int wid  = tid >> 5;
    const int wm   = wid & 3;
    const int wn   = wid >> 2;
    const int brow = blockIdx.y * BM;
    const int bcol = blockIdx.x * BN;

    wmma::fragment<wmma::accumulator, 16, 16, 8, float> acc[2][NF];
#pragma unroll
    for (int i = 0; i < 2; i++)
#pragma unroll
        for (int j = 0; j < NF; j++)
            wmma::fill_fragment(acc[i][j], 0.f);

    const int ar0 = tid >> 2,          ac0 = (tid & 3) * 4;
    const int ar1 = (tid + 256) >> 2,  ac1 = (tid & 3) * 4;

    float4 aR0, aR1;
    float4 bR[BL];

    auto loadA = [&](int k0) {
        aR0 = *(const float4*)&A[(size_t)(brow + ar0) * K + k0 + ac0];
        aR1 = *(const float4*)&A[(size_t)(brow + ar1) * K + k0 + ac1];
    };
    auto loadB = [&](int k0) {
#pragma unroll
        for (int u = 0; u < BL; u++) {
            int idx = tid + 256 * u;
            int r = idx / NB4, c = (idx % NB4) * 4;
            int gc = bcol + c;
            if (gc + 4 <= N) {
                bR[u] = *(const float4*)&B[(size_t)(k0 + r) * N + gc];
            } else {
                float v0 = (gc + 0 < N) ? B[(size_t)(k0 + r) * N + gc + 0] : 0.f;
                float v1 = (gc + 1 < N) ? B[(size_t)(k0 + r) * N + gc + 1] : 0.f;
                float v2 = (gc + 2 < N) ? B[(size_t)(k0 + r) * N + gc + 2] : 0.f;
                float v3 = (gc + 3 < N) ? B[(size_t)(k0 + r) * N + gc + 3] : 0.f;
                bR[u] = make_float4(v0, v1, v2, v3);
            }
        }
    };
    auto storeS = [&](int buf) {
        As[buf][ar0 * LDA + ac0 + 0] = wmma::__float_to_tf32(aR0.x);
        As[buf][ar0 * LDA + ac0 + 1] = wmma::__float_to_tf32(aR0.y);
        As[buf][ar0 * LDA + ac0 + 2] = wmma::__float_to_tf32(aR0.z);
        As[buf][ar0 * LDA + ac0 + 3] = wmma::__float_to_tf32(aR0.w);
        As[buf][ar1 * LDA + ac1 + 0] = wmma::__float_to_tf32(aR1.x);
        As[buf][ar1 * LDA + ac1 + 1] = wmma::__float_to_tf32(aR1.y);
        As[buf][ar1 * LDA + ac1 + 2] = wmma::__float_to_tf32(aR1.z);
        As[buf][ar1 * LDA + ac1 + 3] = wmma::__float_to_tf32(aR1.w);
#pragma unroll
        for (int u = 0; u < BL; u++) {
            int idx = tid + 256 * u;
            int r = idx / NB4, c = (idx % NB4) * 4;
            Bs[buf][r * LDB + c + 0] = wmma::__float_to_tf32(bR[u].x);
            Bs[buf][r * LDB + c + 1] = wmma::__float_to_tf32(bR[u].y);
            Bs[buf][r * LDB + c + 2] = wmma::__float_to_tf32(bR[u].z);
            Bs[buf][r * LDB + c + 3] = wmma::__float_to_tf32(bR[u].w);
        }
    };
    auto compute = [&](int buf) {
#pragma unroll
        for (int kk = 0; kk < BK; kk += 8) {
            wmma::fragment<wmma::matrix_a, 16, 16, 8, wmma::precision::tf32,
                           wmma::row_major> af[2];
            wmma::fragment<wmma::matrix_b, 16, 16, 8, wmma::precision::tf32,
                           wmma::row_major> bf[NF];
#pragma unroll
            for (int i = 0; i < 2; i++)
                wmma::load_matrix_sync(af[i],
                    &As[buf][(wm * 32 + i * 16) * LDA + kk], LDA);
#pragma unroll
            for (int j = 0; j < NF; j++)
                wmma::load_matrix_sync(bf[j],
                    &Bs[buf][kk * LDB + wn * WN + j * 16], LDB);
#pragma unroll
            for (int i = 0; i < 2; i++)
#pragma unroll
                for (int j = 0; j < NF; j++)
                    wmma::mma_sync(acc[i][j], af[i], bf[j], acc[i][j]);
        }
    };

    loadA(0); loadB(0);
    int buf = 0;
    storeS(buf);
    __syncthreads();
    for (int k0 = 0; k0 < K; k0 += BK) {
        bool last = (k0 + BK >= K);
        if (!last) { loadA(k0 + BK); loadB(k0 + BK); }
        compute(buf);
        if (!last) storeS(buf ^ 1);
        __syncthreads();
        buf ^= 1;
    }

    const int er = lane >> 1;
    const int ec = (lane & 1) * 8;
#pragma unroll
    for (int i = 0; i < 2; i++) {
#pragma unroll
        for (int j = 0; j < NF; j++) {
            wmma::store_matrix_sync(Ep[wid], acc[i][j], 16, wmma::mem_row_major);
            __syncwarp();
            int gr = brow + wm * 32 + i * 16 + er;
            int gc = bcol + wn * WN + j * 16 + ec;
            float v[8];
#pragma unroll
            for (int q = 0; q < 8; q++)
                v[q] = Ep[wid][er * 16 + ec + q] +
                       (bias ? ((gc + q < N) ? bias[gc + q] : 0.f) : 0.f);
            if (gc + 8 <= N) {
                *(float4*)&C[(size_t)gr * N + gc]     = make_float4(v[0], v[1], v[2], v[3]);
                *(float4*)&C[(size_t)gr * N + gc + 4] = make_float4(v[4], v[5], v[6], v[7]);
            } else {
#pragma unroll
                for (int q = 0; q < 8; q++)
                    if (gc + q < N) C[(size_t)gr * N + gc + q] = v[q];
            }
            __syncwarp();
        }
    }
}

// ---------------------------------------------------------------------------
// Depthwise causal conv (K=4) + SiLU
// ---------------------------------------------------------------------------
__global__ void conv_silu(const float* __restrict__ cw,
                          const float* __restrict__ cb)
{
    int idx = blockIdx.x * blockDim.x + threadIdx.x;
    if (idx >= ROWS * DI) return;
    int d   = idx & (DI - 1);
    int row = idx >> 9;
    int t   = row & (TT - 1);

    const float* xi = g_xz + (size_t)row * (2 * DI) + d;
    float w0 = cw[d * 4 + 0], w1 = cw[d * 4 + 1];
    float w2 = cw[d * 4 + 2], w3 = cw[d * 4 + 3];

    float acc = cb[d] + w3 * xi[0];
    if (t >= 1) acc += w2 * xi[-(2 * DI)];
    if (t >= 2) acc += w1 * xi[-(4 * DI)];
    if (t >= 3) acc += w0 * xi[-(6 * DI)];

    g_xc[idx] = __fdividef(acc, 1.f + __expf(-acc));
}

// ---------------------------------------------------------------------------
// dt = softplus(dbc[:, :R] @ Wdt + bdt)
// ---------------------------------------------------------------------------
__global__ void dt_softplus(const float* __restrict__ Wdt,
                            const float* __restrict__ bdt)
{
    int idx = blockIdx.x * blockDim.x + threadIdx.x;
    if (idx >= ROWS * DI) return;
    int d   = idx & (DI - 1);
    int row = idx >> 9;

    const float* db = g_dbc + (size_t)row * DBCN;
    float acc = bdt[d];
#pragma unroll
    for (int r = 0; r < RR; r++)
        acc += db[r] * Wdt[r * DI + d];

    g_dt[idx] = (acc > 20.f) ? acc : log1pf(__expf(acc));
}

// ---------------------------------------------------------------------------
// Selective scan, fused with gating.
// 4 threads per (b,d) lane, 4 states per thread.
// Block = 128 threads = 32 d-lanes of one b. Grid = BB*16 = 128.
// Inputs staged through double-buffered smem in 16-step chunks.
// Writes g_y = (scan_y + Dp*xc) * silu(z).
// ---------------------------------------------------------------------------
#define SCH 16
__global__ __launch_bounds__(128) void ssm_scan_fused(
    const float* __restrict__ A_log_l, const float* __restrict__ Dp_l)
{
    __shared__ __align__(16) float s_dt[2][SCH][32];
    __shared__ __align__(16) float s_x [2][SCH][32];
    __shared__ __align__(16) float s_z [2][SCH][32];
    __shared__ __align__(16) float s_bc[2][SCH][32];  // B[0:16] C[16:32]

    const int b   = blockIdx.x >> 4;
    const int dg  = blockIdx.x & 15;
    const int d0  = dg * 32;
    const int tid = threadIdx.x;
    const int q   = tid & 3;        // state quad (n = q*4 .. q*4+3)
    const int dl  = tid >> 2;       // 0..31
    const int d   = d0 + dl;

    // chunk loader mapping
    const int tl  = tid >> 3;       // 0..15 (time within chunk)
    const int seg = tid & 7;        // 0..7  (column segment *4)

    float a[4];
#pragma unroll
    for (int j = 0; j < 4; j++)
        a[j] = -__expf(A_log_l[d * NST + q * 4 + j]);
    const float dp = Dp_l[d];

    const size_t rb = (size_t)b * TT;   // global row base

    float h0 = 0.f, h1 = 0.f, h2 = 0.f, h3 = 0.f;

    // preload chunk 0
    {
        size_t row = rb + tl;
        float4 vdt = *(const float4*)&g_dt [row * DI + d0 + seg * 4];
        float4 vx  = *(const float4*)&g_xc [row * DI + d0 + seg * 4];
        float4 vz  = *(const float4*)&g_xz [row * (2 * DI) + DI + d0 + seg * 4];
        float4 vbc = *(const float4*)&g_dbc[row * DBCN + RR + seg * 4];
        *(float4*)&s_dt[0][tl][seg * 4] = vdt;
        *(float4*)&s_x [0][tl][seg * 4] = vx;
        *(float4*)&s_z [0][tl][seg * 4] = vz;
        *(float4*)&s_bc[0][tl][seg * 4] = vbc;
    }
    __syncthreads();

    int buf = 0;
    const int NC = TT / SCH;
    for (int c = 0; c < NC; c++) {
        // prefetch next chunk into registers (overlaps with compute)
        float4 vdt, vx, vz, vbc;
        const bool more = (c + 1 < NC);
        if (more) {
            size_t row = rb + (size_t)(c + 1) * SCH + tl;
            vdt = *(const float4*)&g_dt [row * DI + d0 + seg * 4];
            vx  = *(const float4*)&g_xc [row * DI + d0 + seg * 4];
            vz  = *(const float4*)&g_xz [row * (2 * DI) + DI + d0 + seg * 4];
            vbc = *(const float4*)&g_dbc[row * DBCN + RR + seg * 4];
        }

        // compute SCH steps from smem[buf]
#pragma unroll
        for (int it = 0; it < SCH; it++) {
            float dt = s_dt[buf][it][dl];
            float x  = s_x [buf][it][dl];
            float4 Bv = *(const float4*)&s_bc[buf][it][q * 4];
            float4 Cv = *(const float4*)&s_bc[buf][it][16 + q * 4];
            float z  = s_z [buf][it][dl];

            float dtx = dt * x;
            h0 = __expf(dt * a[0]) * h0 + dtx * Bv.x;
            h1 = __expf(dt * a[1]) * h1 + dtx * Bv.y;
            h2 = __expf(dt * a[2]) * h2 + dtx * Bv.z;
            h3 = __expf(dt * a[3]) * h3 + dtx * Bv.w;

            float pv = h0 * Cv.x + h1 * Cv.y + h2 * Cv.z + h3 * Cv.w;
            pv += __shfl_xor_sync(0xffffffffu, pv, 1);
            pv += __shfl_xor_sync(0xffffffffu, pv, 2);

            if (q == 0) {
                float sz = __fdividef(z, 1.f + __expf(-z));
                size_t row = rb + (size_t)c * SCH + it;
                g_y[row * DI + d] = (pv + dp * x) * sz;
            }
        }

        if (more) {
            *(float4*)&s_dt[buf ^ 1][tl][seg * 4] = vdt;
            *(float4*)&s_x [buf ^ 1][tl][seg * 4] = vx;
            *(float4*)&s_z [buf ^ 1][tl][seg * 4] = vz;
            *(float4*)&s_bc[buf ^ 1][tl][seg * 4] = vbc;
        }
        __syncthreads();
        buf ^= 1;
    }
}

// ---------------------------------------------------------------------------
// Final: mean over T, then @ W_out_proj + b_out_proj
// ---------------------------------------------------------------------------
__global__ void mean_proj(const float* __restrict__ Wop,
                          const float* __restrict__ bop,
                          float* __restrict__ out)
{
    __shared__ float hm[DM];
    int b = blockIdx.x;
    int c = threadIdx.x;

    float s = 0.f;
    const float* hp = g_h + (size_t)b * TT * DM + c;
    for (int t = 0; t < TT; t++)
        s += hp[(size_t)t * DM];
    hm[c] = s * (1.f / (float)TT);
    __syncthreads();

    if (c < DOUT) {
        float acc = bop[c];
#pragma unroll 4
        for (int k = 0; k < DM; k++)
            acc += hm[k] * Wop[k * DOUT + c];
        out[b * DOUT + c] = acc;
    }
}

// ---------------------------------------------------------------------------
// Orchestration
// ---------------------------------------------------------------------------
static void launch_tgemm128(const float* A, const float* B, const float* bias,
                            float* C, int M, int N, int K)
{
    dim3 grid((N + 127) / 128, (M + 127) / 128);
    tgemm<128><<<grid, 256>>>(A, B, bias, C, M, N, K);
}
static void launch_tgemm64(const float* A, const float* B, const float* bias,
                           float* C, int M, int N, int K)
{
    dim3 grid((N + 63) / 64, (M + 127) / 128);
    tgemm<64><<<grid, 256>>>(A, B, bias, C, M, N, K);
}

extern "C" void kernel_launch(void* const* d_in, const int* in_sizes, int n_in,
                              void* d_out, int out_size)
{
    const float* x        = (const float*)d_in[0];
    const float* W_in     = (const float*)d_in[1];
    const float* b_in     = (const float*)d_in[2];
    const float* Win      = (const float*)d_in[3];
    const float* bin_     = (const float*)d_in[4];
    const float* conv_w   = (const float*)d_in[5];
    const float* conv_b   = (const float*)d_in[6];
    const float* Wx       = (const float*)d_in[7];
    const float* Wdt      = (const float*)d_in[8];
    const float* bdt      = (const float*)d_in[9];
    const float* A_log    = (const float*)d_in[10];
    const float* Dp       = (const float*)d_in[11];
    const float* Wout     = (const float*)d_in[12];
    const float* W_op     = (const float*)d_in[13];
    const float* b_op     = (const float*)d_in[14];
    float* out = (float*)d_out;

    float *hbuf, *xzbuf, *xcbuf, *dbcbuf, *ybuf;
    cudaGetSymbolAddress((void**)&hbuf,   g_h);
    cudaGetSymbolAddress((void**)&xzbuf,  g_xz);
    cudaGetSymbolAddress((void**)&xcbuf,  g_xc);
    cudaGetSymbolAddress((void**)&dbcbuf, g_dbc);
    cudaGetSymbolAddress((void**)&ybuf,   g_y);

    const int EW_BLOCKS = (ROWS * DI + 255) / 256;

    // in_proj
    launch_tgemm128(x, W_in, b_in, hbuf, ROWS, DM, DIN);

    for (int l = 0; l < LAY; l++) {
        const float* Win_l  = Win    + (size_t)l * DM * 2 * DI;
        const float* bin_l  = bin_   + (size_t)l * 2 * DI;
        const float* cw_l   = conv_w + (size_t)l * DI * 4;
        const float* cb_l   = conv_b + (size_t)l * DI;
        const float* Wx_l   = Wx     + (size_t)l * DI * DBCN;
        const float* Wdt_l  = Wdt    + (size_t)l * RR * DI;
        const float* bdt_l  = bdt    + (size_t)l * DI;
        const float* Alog_l = A_log  + (size_t)l * DI * NST;
        const float* Dp_l   = Dp     + (size_t)l * DI;
        const float* Wout_l = Wout   + (size_t)l * DI * DM;

        launch_tgemm128(hbuf, Win_l, bin_l, xzbuf, ROWS, 2 * DI, DM);
        conv_silu<<<EW_BLOCKS, 256>>>(cw_l, cb_l);
        launch_tgemm64(xcbuf, Wx_l, nullptr, dbcbuf, ROWS, DBCN, DI);
        dt_softplus<<<EW_BLOCKS, 256>>>(Wdt_l, bdt_l);
        // scan + gating fused
        ssm_scan_fused<<<BB * (DI / 32), 128>>>(Alog_l, Dp_l);
        launch_tgemm128(ybuf, Wout_l, nullptr, hbuf, ROWS, DM, DI);
    }

    mean_proj<<<BB, DM>>>(W_op, b_op, out);
}